// round 1
// baseline (speedup 1.0000x reference)
#include <cuda_runtime.h>
#include <math.h>

#define BATCH 4096
#define UNITS 1024
#define G4 (4*UNITS)
#define OUT_STEPS 200
#define SEQ_LEN 5

// Persistent state (device globals — no allocation allowed)
__device__ float g_h[2][BATCH*UNITS];   // ping-pong hidden state
__device__ float g_c[BATCH*UNITS];      // cell state (updated in place)
__device__ float g_pred[BATCH];         // autoregressive feedback value

__global__ void zero_kernel() {
    int i = blockIdx.x * blockDim.x + threadIdx.x;
    if (i < BATCH*UNITS) { g_h[0][i] = 0.0f; g_c[i] = 0.0f; }
}

// Fused LSTM step: z = x@K + h@R + b ; gates ; c,h update.
// Tile: BM=64 batch rows x BN=64 units (x4 gates = 256 cols of z).
#define BM 64
#define BN 64
#define BK 16

__global__ __launch_bounds__(256, 2) void lstm_step(
    const float* __restrict__ xsrc, int xstride,   // x[b] = xsrc[b*xstride]; xsrc==null -> g_pred
    const float* __restrict__ Kw,                  // [4U] input kernel (F=1)
    const float* __restrict__ R,                   // [U][4U] recurrent kernel
    const float* __restrict__ bias,                // [4U]
    int pin)                                       // read parity
{
    __shared__ float sh[BK][BM];        // h tile, transposed: sh[k][m]
    __shared__ float sr[BK][4*BN];      // R tile: sr[k][gate*64 + u]

    const float* __restrict__ h_in = g_h[pin];
    float* __restrict__ h_out = g_h[pin ^ 1];
    const float* __restrict__ xs = xsrc ? xsrc : g_pred;
    int xst = xsrc ? xstride : 1;

    const int bm0 = blockIdx.x * BM;
    const int un0 = blockIdx.y * BN;
    const int t   = threadIdx.x;          // 0..255
    const int ty  = t >> 4;               // 0..15 (batch group)
    const int tx  = t & 15;               // 0..15 (unit group)
    const int m0  = ty * 4;
    const int u0l = tx * 4;

    float acc[4][4][4];                   // [gate][m][u]
    #pragma unroll
    for (int g = 0; g < 4; g++)
        #pragma unroll
        for (int m = 0; m < 4; m++)
            #pragma unroll
            for (int u = 0; u < 4; u++) acc[g][m][u] = 0.0f;

    const int lh_m = t >> 2;              // 0..63
    const int lh_k = (t & 3) * 4;         // 0,4,8,12

    for (int k0 = 0; k0 < UNITS; k0 += BK) {
        // Load h tile (64x16), transpose into sh[k][m]
        float4 hv = *reinterpret_cast<const float4*>(&h_in[(bm0 + lh_m)*UNITS + k0 + lh_k]);
        sh[lh_k+0][lh_m] = hv.x;
        sh[lh_k+1][lh_m] = hv.y;
        sh[lh_k+2][lh_m] = hv.z;
        sh[lh_k+3][lh_m] = hv.w;
        // Load R tile: 16 rows x 256 cols (4 gate chunks of 64) = 1024 float4
        #pragma unroll
        for (int r = 0; r < 4; r++) {
            int idx  = t + r * 256;       // 0..1023
            int kk   = idx >> 6;
            int rest = idx & 63;
            int gg   = rest >> 4;
            int uu   = (rest & 15) * 4;
            float4 rv = *reinterpret_cast<const float4*>(
                &R[(k0 + kk)*G4 + gg*UNITS + un0 + uu]);
            *reinterpret_cast<float4*>(&sr[kk][gg*BN + uu]) = rv;
        }
        __syncthreads();

        #pragma unroll
        for (int kk = 0; kk < BK; kk++) {
            float4 hv4 = *reinterpret_cast<const float4*>(&sh[kk][m0]);
            float hr[4] = {hv4.x, hv4.y, hv4.z, hv4.w};
            float rr[4][4];
            #pragma unroll
            for (int g = 0; g < 4; g++) {
                float4 rv4 = *reinterpret_cast<const float4*>(&sr[kk][g*BN + u0l]);
                rr[g][0] = rv4.x; rr[g][1] = rv4.y; rr[g][2] = rv4.z; rr[g][3] = rv4.w;
            }
            #pragma unroll
            for (int g = 0; g < 4; g++)
                #pragma unroll
                for (int m = 0; m < 4; m++)
                    #pragma unroll
                    for (int u = 0; u < 4; u++)
                        acc[g][m][u] = fmaf(hr[m], rr[g][u], acc[g][m][u]);
        }
        __syncthreads();
    }

    // Epilogue: add x@K + bias, apply gates, update c and h
    #pragma unroll
    for (int m = 0; m < 4; m++) {
        int b = bm0 + m0 + m;
        float xb = xs[b * xst];
        #pragma unroll
        for (int u = 0; u < 4; u++) {
            int un = un0 + u0l + u;
            float zi = acc[0][m][u] + xb * Kw[un]           + bias[un];
            float zf = acc[1][m][u] + xb * Kw[UNITS   + un] + bias[UNITS   + un];
            float zg = acc[2][m][u] + xb * Kw[2*UNITS + un] + bias[2*UNITS + un];
            float zo = acc[3][m][u] + xb * Kw[3*UNITS + un] + bias[3*UNITS + un];
            float ig = 1.0f / (1.0f + __expf(-zi));
            float fg = 1.0f / (1.0f + __expf(-zf));
            float gg = tanhf(zg);
            float og = 1.0f / (1.0f + __expf(-zo));
            int off = b * UNITS + un;
            float cnew = fg * g_c[off] + ig * gg;
            g_c[off] = cnew;
            h_out[off] = og * tanhf(cnew);
        }
    }
}

// Dense head: x1 = relu(h@w1 + b1); pred = final_dense ? x1*w2+b2 : x1
// One warp per batch row.
__global__ __launch_bounds__(256) void pred_kernel(
    const float* __restrict__ w1, const float* __restrict__ b1,
    const float* __restrict__ w2, const float* __restrict__ b2,
    float* __restrict__ out, int tcol, int pin, int final_dense)
{
    int warp = (blockIdx.x * blockDim.x + threadIdx.x) >> 5;
    int lane = threadIdx.x & 31;
    if (warp >= BATCH) return;
    const float* __restrict__ hr = &g_h[pin][warp * UNITS];
    float s = 0.0f;
    #pragma unroll 4
    for (int k = lane; k < UNITS; k += 32) s = fmaf(hr[k], w1[k], s);
    #pragma unroll
    for (int off = 16; off; off >>= 1) s += __shfl_down_sync(0xffffffffu, s, off);
    if (lane == 0) {
        float x = fmaxf(s + b1[0], 0.0f);
        float p = final_dense ? fmaf(x, w2[0], b2[0]) : x;
        out[warp * OUT_STEPS + tcol] = p;
        g_pred[warp] = p;
    }
}

extern "C" void kernel_launch(void* const* d_in, const int* in_sizes, int n_in,
                              void* d_out, int out_size)
{
    const float* inputs = (const float*)d_in[0];   // [B, 5, 1]
    const float* Kw     = (const float*)d_in[1];   // [1, 4U]
    const float* R      = (const float*)d_in[2];   // [U, 4U]
    const float* bias   = (const float*)d_in[3];   // [4U]
    const float* w1     = (const float*)d_in[4];   // [U, 1]
    const float* b1     = (const float*)d_in[5];   // [1]
    const float* w2     = (const float*)d_in[6];   // [1, 1]
    const float* b2     = (const float*)d_in[7];   // [1]
    float* out = (float*)d_out;                    // [B, 200, 1]

    zero_kernel<<<(BATCH*UNITS + 255)/256, 256>>>();

    dim3 grid(BATCH/BM, UNITS/BN);   // (64, 16)
    int pp = 0;

    // Warmup over input sequence
    for (int t = 0; t < SEQ_LEN; t++) {
        lstm_step<<<grid, 256>>>(inputs + t, SEQ_LEN, Kw, R, bias, pp);
        pp ^= 1;
    }
    // First prediction: dense1 only
    pred_kernel<<<BATCH/8, 256>>>(w1, b1, w2, b2, out, 0, pp, 0);

    // Autoregressive decode
    for (int j = 1; j < OUT_STEPS; j++) {
        lstm_step<<<grid, 256>>>(nullptr, 1, Kw, R, bias, pp);
        pp ^= 1;
        pred_kernel<<<BATCH/8, 256>>>(w1, b1, w2, b2, out, j, pp, 1);
    }
}

// round 4
// speedup vs baseline: 2.0268x; 2.0268x over previous
#include <cuda_runtime.h>
#include <cuda_bf16.h>
#include <math.h>
#include <cstdint>

#define BATCH 4096
#define UNITS 1024
#define OUT_STEPS 200
#define SEQ_LEN 5

#define KTOT 3072        // [h_hi | h_hi | h_lo] x [R_hi ; R_lo ; R_hi]
#define BK 64
#define NSTG (KTOT / BK) // 48
#define BM 128
#define BN 256           // permuted z columns (= 64 units x 4 gates)

#define A_STG (BM * BK * 2)             // 16KB
#define B_STG (BN * BK * 2)             // 32KB
#define STG_BYTES (A_STG + B_STG)       // 48KB
#define SMEM_TOTAL (2 * STG_BYTES)      // 96KB

// ---------------- device globals ----------------
__device__ __nv_bfloat16 g_A[2][BATCH * 2048]; // ping-pong: [b][0:1024)=h_hi, [1024:2048)=h_lo
__device__ __nv_bfloat16 g_B[4096 * KTOT];     // permuted split R, row C, K-major
__device__ float g_c[BATCH * UNITS];
__device__ float g_pred[BATCH];
__device__ float g_kwP[4096];
__device__ float g_biasP[4096];

// ---------------- helpers ----------------
__device__ __forceinline__ uint32_t smem_u32(const void* p) {
    uint32_t a;
    asm("{ .reg .u64 t; cvta.to.shared.u64 t, %1; cvt.u32.u64 %0, t; }" : "=r"(a) : "l"(p));
    return a;
}
__device__ __forceinline__ void cp16(uint32_t saddr, const void* gaddr) {
    asm volatile("cp.async.cg.shared.global [%0], [%1], 16;" :: "r"(saddr), "l"(gaddr));
}
__device__ __forceinline__ void cp_commit() {
    asm volatile("cp.async.commit_group;" ::: "memory");
}
template<int N> __device__ __forceinline__ void cp_wait() {
    asm volatile("cp.async.wait_group %0;" :: "n"(N) : "memory");
}
__device__ __forceinline__ void ldsm4(uint32_t* r, uint32_t addr) {
    asm volatile("ldmatrix.sync.aligned.m8n8.x4.shared.b16 {%0,%1,%2,%3}, [%4];"
                 : "=r"(r[0]), "=r"(r[1]), "=r"(r[2]), "=r"(r[3]) : "r"(addr));
}
__device__ __forceinline__ void mma16816(float* c, const uint32_t* a, const uint32_t* b) {
    asm volatile(
        "mma.sync.aligned.m16n8k16.row.col.f32.bf16.bf16.f32 "
        "{%0,%1,%2,%3}, {%4,%5,%6,%7}, {%8,%9}, {%0,%1,%2,%3};"
        : "+f"(c[0]), "+f"(c[1]), "+f"(c[2]), "+f"(c[3])
        : "r"(a[0]), "r"(a[1]), "r"(a[2]), "r"(a[3]), "r"(b[0]), "r"(b[1]));
}
__device__ __forceinline__ float sigm(float x) { return 1.0f / (1.0f + __expf(-x)); }
__device__ __forceinline__ float tanh_fast(float x) {
    float t = __expf(-2.0f * fabsf(x));
    float r = (1.0f - t) / (1.0f + t);
    return copysignf(r, x);
}

// ---------------- prep: build permuted split-bf16 B ----------------
// Permuted column C <- (unit u, gate g):
//   C = (u>>4)*64 + (g>>1)*32 + (u&3)*8 + ((u>>2)&3)*2 + (g&1)
// Inverse: u = (C>>6)*16 + ((C>>1)&3)*4 + ((C>>3)&3) ; g = ((C>>5)&1)*2 + (C&1)
__global__ void prep_kernel(const float* __restrict__ R, const float* __restrict__ Kw,
                            const float* __restrict__ bias) {
    int idx = blockIdx.x * blockDim.x + threadIdx.x;   // np*1024 + k
    if (idx >= 4096 * 1024) return;
    int np = idx >> 10;
    int k  = idx & 1023;
    int u = ((np >> 6) << 4) | (((np >> 1) & 3) << 2) | ((np >> 3) & 3);
    int g = (((np >> 5) & 1) << 1) | (np & 1);
    int n = g * 1024 + u;
    float v = R[k * 4096 + n];
    __nv_bfloat16 hi = __float2bfloat16(v);
    __nv_bfloat16 lo = __float2bfloat16(v - __bfloat162float(hi));
    g_B[np * KTOT + k]        = hi;
    g_B[np * KTOT + 1024 + k] = lo;
    g_B[np * KTOT + 2048 + k] = hi;
    if (k == 0) { g_kwP[np] = Kw[n]; g_biasP[np] = bias[n]; }
}

__global__ void zero_kernel() {
    int i = blockIdx.x * blockDim.x + threadIdx.x;
    if (i < BATCH * UNITS) {
        ((uint32_t*)g_A[0])[i] = 0;   // 4M u32 = all 8M bf16 of g_A[0]
        g_c[i] = 0.0f;
    }
}

// ---------------- fused LSTM step (bf16 mma.sync GEMM + gates) ----------------
__global__ void __launch_bounds__(256, 1) lstm_mma(const float* __restrict__ xsrc, int xstride,
                                                   int pin) {
    extern __shared__ char smem[];
    const uint32_t sb = smem_u32(smem);
    const int tid  = threadIdx.x;
    const int wid  = tid >> 5;
    const int lane = tid & 31;
    const int wm   = wid >> 2;       // 0..1
    const int wn   = wid & 3;        // 0..3
    const int m0   = blockIdx.x * BM;
    const int n0p  = blockIdx.y * BN;   // permuted-col base

    const __nv_bfloat16* __restrict__ Ain = g_A[pin];
    __nv_bfloat16* __restrict__ Aout = g_A[pin ^ 1];

    float acc[4][8][4];
    #pragma unroll
    for (int a = 0; a < 4; a++)
        #pragma unroll
        for (int b = 0; b < 8; b++)
            #pragma unroll
            for (int c = 0; c < 4; c++) acc[a][b][c] = 0.0f;

    const int cprow = tid >> 3;     // base row, step 32
    const int cpch  = tid & 7;

    auto issue = [&](int s) {
        const int buf = s & 1;
        const int kA = (s & 15) * BK + ((s >= 32) ? 1024 : 0);
        const int kB = s * BK;
        const uint32_t ab = sb + buf * STG_BYTES;
        const uint32_t bb = ab + A_STG;
        #pragma unroll
        for (int p = 0; p < 4; p++) {                 // A: 128 rows
            int row = cprow + p * 32;
            uint32_t sa = ab + row * 128 + ((cpch ^ (row & 7)) << 4);
            cp16(sa, &Ain[(m0 + row) * 2048 + kA + cpch * 8]);
        }
        #pragma unroll
        for (int p = 0; p < 8; p++) {                 // B: 256 rows
            int row = cprow + p * 32;
            uint32_t sa = bb + row * 128 + ((cpch ^ (row & 7)) << 4);
            cp16(sa, &g_B[(uint64_t)(n0p + row) * KTOT + kB + cpch * 8]);
        }
        cp_commit();
    };

    issue(0);

    for (int s = 0; s < NSTG; s++) {
        if (s + 1 < NSTG) { issue(s + 1); cp_wait<1>(); }
        else              { cp_wait<0>(); }
        __syncthreads();

        const int buf = s & 1;
        const uint32_t ab = sb + buf * STG_BYTES;
        const uint32_t bb = ab + A_STG;

        #pragma unroll
        for (int kk = 0; kk < 4; kk++) {
            uint32_t af[4][4], bf4[4][4];
            {
                int r  = (lane & 15);
                int ch = kk * 2 + (lane >> 4);
                #pragma unroll
                for (int mi = 0; mi < 4; mi++) {
                    int row = wm * 64 + mi * 16 + r;
                    ldsm4(af[mi], ab + row * 128 + (((ch ^ (row & 7))) << 4));
                }
            }
            {
                int rr = (lane & 7) + ((lane >> 4) << 3);
                int ch = kk * 2 + ((lane >> 3) & 1);
                #pragma unroll
                for (int jp = 0; jp < 4; jp++) {
                    int row = wn * 64 + jp * 16 + rr;
                    ldsm4(bf4[jp], bb + row * 128 + (((ch ^ (row & 7))) << 4));
                }
            }
            #pragma unroll
            for (int mi = 0; mi < 4; mi++)
                #pragma unroll
                for (int j = 0; j < 8; j++)
                    mma16816(acc[mi][j], af[mi], &bf4[j >> 1][(j & 1) * 2]);
        }
        __syncthreads();
    }

    // ---------------- epilogue ----------------
    const int q  = lane & 3;
    const int tr = lane >> 2;
    float kwv[8][2], bsv[8][2];
    #pragma unroll
    for (int j = 0; j < 8; j++) {
        int C = n0p + wn * 64 + 8 * j + 2 * q;
        float2 kw2 = *reinterpret_cast<const float2*>(&g_kwP[C]);
        float2 bs2 = *reinterpret_cast<const float2*>(&g_biasP[C]);
        kwv[j][0] = kw2.x; kwv[j][1] = kw2.y;
        bsv[j][0] = bs2.x; bsv[j][1] = bs2.y;
    }
    const int u0 = (blockIdx.y * 64) + wn * 16 + 4 * q;   // 4 consecutive units

    #pragma unroll
    for (int mi = 0; mi < 4; mi++) {
        #pragma unroll
        for (int h = 0; h < 2; h++) {
            int row = m0 + wm * 64 + mi * 16 + tr + 8 * h;
            float xb = xsrc ? xsrc[row * xstride] : g_pred[row];
            float4 cold = *reinterpret_cast<const float4*>(&g_c[row * 1024 + u0]);
            float co[4] = {cold.x, cold.y, cold.z, cold.w};
            float cn[4];
            __nv_bfloat16 hh_hi[4], hh_lo[4];
            #pragma unroll
            for (int jl = 0; jl < 4; jl++) {
                float zi = acc[mi][jl    ][2 * h    ] + xb * kwv[jl    ][0] + bsv[jl    ][0];
                float zf = acc[mi][jl    ][2 * h + 1] + xb * kwv[jl    ][1] + bsv[jl    ][1];
                float zg = acc[mi][jl + 4][2 * h    ] + xb * kwv[jl + 4][0] + bsv[jl + 4][0];
                float zo = acc[mi][jl + 4][2 * h + 1] + xb * kwv[jl + 4][1] + bsv[jl + 4][1];
                float ig = sigm(zi);
                float fg = sigm(zf);
                float gg = tanh_fast(zg);
                float og = sigm(zo);
                float cc = fg * co[jl] + ig * gg;
                cn[jl] = cc;
                float hh = og * tanh_fast(cc);
                __nv_bfloat16 hi = __float2bfloat16(hh);
                hh_hi[jl] = hi;
                hh_lo[jl] = __float2bfloat16(hh - __bfloat162float(hi));
            }
            float4 cv = {cn[0], cn[1], cn[2], cn[3]};
            *reinterpret_cast<float4*>(&g_c[row * 1024 + u0]) = cv;
            uint2 hv, lv;
            memcpy(&hv, hh_hi, 8);
            memcpy(&lv, hh_lo, 8);
            *reinterpret_cast<uint2*>(&Aout[row * 2048 + u0])        = hv;
            *reinterpret_cast<uint2*>(&Aout[row * 2048 + 1024 + u0]) = lv;
        }
    }
}

// ---------------- prediction head ----------------
__global__ void __launch_bounds__(256) pred_kernel(
    const float* __restrict__ w1, const float* __restrict__ b1,
    const float* __restrict__ w2, const float* __restrict__ b2,
    float* __restrict__ out, int tcol, int pin, int final_dense)
{
    int warp = (blockIdx.x * blockDim.x + threadIdx.x) >> 5;
    int lane = threadIdx.x & 31;
    if (warp >= BATCH) return;
    const __nv_bfloat16* __restrict__ ha = &g_A[pin][warp * 2048];
    float s = 0.0f;
    #pragma unroll 4
    for (int k = lane; k < UNITS; k += 32) {
        float h = __bfloat162float(ha[k]) + __bfloat162float(ha[1024 + k]);
        s = fmaf(h, w1[k], s);
    }
    #pragma unroll
    for (int off = 16; off; off >>= 1) s += __shfl_down_sync(0xffffffffu, s, off);
    if (lane == 0) {
        float x = fmaxf(s + b1[0], 0.0f);
        float p = final_dense ? fmaf(x, w2[0], b2[0]) : x;
        out[warp * OUT_STEPS + tcol] = p;
        g_pred[warp] = p;
    }
}

extern "C" void kernel_launch(void* const* d_in, const int* in_sizes, int n_in,
                              void* d_out, int out_size)
{
    const float* inputs = (const float*)d_in[0];
    const float* Kw     = (const float*)d_in[1];
    const float* R      = (const float*)d_in[2];
    const float* bias   = (const float*)d_in[3];
    const float* w1     = (const float*)d_in[4];
    const float* b1     = (const float*)d_in[5];
    const float* w2     = (const float*)d_in[6];
    const float* b2     = (const float*)d_in[7];
    float* out = (float*)d_out;

    cudaFuncSetAttribute(lstm_mma, cudaFuncAttributeMaxDynamicSharedMemorySize, SMEM_TOTAL);

    zero_kernel<<<(BATCH * UNITS + 255) / 256, 256>>>();
    prep_kernel<<<(4096 * 1024 + 255) / 256, 256>>>(R, Kw, bias);

    dim3 grid(BATCH / BM, 4096 / BN);   // (32, 16)
    int pp = 0;

    for (int t = 0; t < SEQ_LEN; t++) {
        lstm_mma<<<grid, 256, SMEM_TOTAL>>>(inputs + t, SEQ_LEN, pp);
        pp ^= 1;
    }
    pred_kernel<<<BATCH / 8, 256>>>(w1, b1, w2, b2, out, 0, pp, 0);

    for (int j = 1; j < OUT_STEPS; j++) {
        lstm_mma<<<grid, 256, SMEM_TOTAL>>>(nullptr, 1, pp);
        pp ^= 1;
        pred_kernel<<<BATCH / 8, 256>>>(w1, b1, w2, b2, out, j, pp, 1);
    }
}

// round 5
// speedup vs baseline: 2.0627x; 1.0177x over previous
#include <cuda_runtime.h>
#include <cuda_bf16.h>
#include <math.h>
#include <cstdint>

#define BATCH 4096
#define UNITS 1024
#define OUT_STEPS 200
#define SEQ_LEN 5

#define KTOT 3072        // [h_hi | h_hi | h_lo] x [R_hi ; R_lo ; R_hi]
#define BK 64
#define NSTG (KTOT / BK) // 48
#define BM 128
#define BN 256           // permuted z columns (= 64 units x 4 gates)

#define A_STG (BM * BK * 2)             // 16KB
#define B_STG (BN * BK * 2)             // 32KB
#define STG_BYTES (A_STG + B_STG)       // 48KB
#define NBUF 3
#define SMEM_TOTAL (NBUF * STG_BYTES)   // 144KB

// ---------------- device globals ----------------
__device__ __nv_bfloat16 g_A[2][BATCH * 2048]; // ping-pong: [b][0:1024)=h_hi, [1024:2048)=h_lo
__device__ __nv_bfloat16 g_B[4096 * KTOT];     // permuted split R, row C, K-major
__device__ float g_c[BATCH * UNITS];
__device__ float g_pred[BATCH];
__device__ float g_kwP[4096];
__device__ float g_biasP[4096];

// ---------------- helpers ----------------
__device__ __forceinline__ uint32_t smem_u32(const void* p) {
    uint32_t a;
    asm("{ .reg .u64 t; cvta.to.shared.u64 t, %1; cvt.u32.u64 %0, t; }" : "=r"(a) : "l"(p));
    return a;
}
__device__ __forceinline__ void cp16(uint32_t saddr, const void* gaddr) {
    asm volatile("cp.async.cg.shared.global [%0], [%1], 16;" :: "r"(saddr), "l"(gaddr));
}
__device__ __forceinline__ void cp_commit() {
    asm volatile("cp.async.commit_group;" ::: "memory");
}
template<int N> __device__ __forceinline__ void cp_wait() {
    asm volatile("cp.async.wait_group %0;" :: "n"(N) : "memory");
}
__device__ __forceinline__ void ldsm4(uint32_t* r, uint32_t addr) {
    asm volatile("ldmatrix.sync.aligned.m8n8.x4.shared.b16 {%0,%1,%2,%3}, [%4];"
                 : "=r"(r[0]), "=r"(r[1]), "=r"(r[2]), "=r"(r[3]) : "r"(addr));
}
__device__ __forceinline__ void mma16816(float* c, const uint32_t* a, const uint32_t* b) {
    asm volatile(
        "mma.sync.aligned.m16n8k16.row.col.f32.bf16.bf16.f32 "
        "{%0,%1,%2,%3}, {%4,%5,%6,%7}, {%8,%9}, {%0,%1,%2,%3};"
        : "+f"(c[0]), "+f"(c[1]), "+f"(c[2]), "+f"(c[3])
        : "r"(a[0]), "r"(a[1]), "r"(a[2]), "r"(a[3]), "r"(b[0]), "r"(b[1]));
}
__device__ __forceinline__ float sigm(float x) { return 1.0f / (1.0f + __expf(-x)); }
__device__ __forceinline__ float tanh_fast(float x) {
    float t = __expf(-2.0f * fabsf(x));
    float r = (1.0f - t) / (1.0f + t);
    return copysignf(r, x);
}

// ---------------- prep: build permuted split-bf16 B ----------------
// Permuted column C <- (unit u, gate g):
//   C = (u>>4)*64 + (g>>1)*32 + (u&3)*8 + ((u>>2)&3)*2 + (g&1)
// Inverse: u = (C>>6)*16 + ((C>>1)&3)*4 + ((C>>3)&3) ; g = ((C>>5)&1)*2 + (C&1)
__global__ void prep_kernel(const float* __restrict__ R, const float* __restrict__ Kw,
                            const float* __restrict__ bias) {
    int idx = blockIdx.x * blockDim.x + threadIdx.x;   // np*1024 + k
    if (idx >= 4096 * 1024) return;
    int np = idx >> 10;
    int k  = idx & 1023;
    int u = ((np >> 6) << 4) | (((np >> 1) & 3) << 2) | ((np >> 3) & 3);
    int g = (((np >> 5) & 1) << 1) | (np & 1);
    int n = g * 1024 + u;
    float v = R[k * 4096 + n];
    __nv_bfloat16 hi = __float2bfloat16(v);
    __nv_bfloat16 lo = __float2bfloat16(v - __bfloat162float(hi));
    g_B[np * KTOT + k]        = hi;
    g_B[np * KTOT + 1024 + k] = lo;
    g_B[np * KTOT + 2048 + k] = hi;
    if (k == 0) { g_kwP[np] = Kw[n]; g_biasP[np] = bias[n]; }
}

__global__ void zero_kernel() {
    int i = blockIdx.x * blockDim.x + threadIdx.x;
    if (i < BATCH * UNITS) {
        ((uint32_t*)g_A[0])[i] = 0;   // 4M u32 = all 8M bf16 of g_A[0]
        g_c[i] = 0.0f;
    }
}

// ---------------- fused LSTM step (bf16 mma.sync GEMM + gates) ----------------
__global__ void __launch_bounds__(256, 1) lstm_mma(const float* __restrict__ xsrc, int xstride,
                                                   int pin) {
    extern __shared__ char smem[];
    const uint32_t sb = smem_u32(smem);
    const int tid  = threadIdx.x;
    const int wid  = tid >> 5;
    const int lane = tid & 31;
    const int wm   = wid >> 2;       // 0..1
    const int wn   = wid & 3;        // 0..3
    const int m0   = blockIdx.x * BM;
    const int n0p  = blockIdx.y * BN;   // permuted-col base

    const __nv_bfloat16* __restrict__ Ain = g_A[pin];
    __nv_bfloat16* __restrict__ Aout = g_A[pin ^ 1];

    float acc[4][8][4];
    #pragma unroll
    for (int a = 0; a < 4; a++)
        #pragma unroll
        for (int b = 0; b < 8; b++)
            #pragma unroll
            for (int c = 0; c < 4; c++) acc[a][b][c] = 0.0f;

    const int cprow = tid >> 3;     // base row, step 32
    const int cpch  = tid & 7;

    auto issue = [&](int s) {
        const int buf = s % NBUF;
        const int kA = (s & 15) * BK + ((s >= 32) ? 1024 : 0);
        const int kB = s * BK;
        const uint32_t ab = sb + buf * STG_BYTES;
        const uint32_t bb = ab + A_STG;
        #pragma unroll
        for (int p = 0; p < 4; p++) {                 // A: 128 rows
            int row = cprow + p * 32;
            uint32_t sa = ab + row * 128 + ((cpch ^ (row & 7)) << 4);
            cp16(sa, &Ain[(m0 + row) * 2048 + kA + cpch * 8]);
        }
        #pragma unroll
        for (int p = 0; p < 8; p++) {                 // B: 256 rows
            int row = cprow + p * 32;
            uint32_t sa = bb + row * 128 + ((cpch ^ (row & 7)) << 4);
            cp16(sa, &g_B[(uint64_t)(n0p + row) * KTOT + kB + cpch * 8]);
        }
        cp_commit();
    };

    // fragment loaders (kk = 16-element k-chunk index within the stage)
    const int a_r  = lane & 15;
    const int a_cb = lane >> 4;
    const int b_rr = (lane & 7) + ((lane >> 4) << 3);
    const int b_cb = (lane >> 3) & 1;

    auto load_afrag = [&](uint32_t ab, int kk, uint32_t af[4][4]) {
        int ch = kk * 2 + a_cb;
        #pragma unroll
        for (int mi = 0; mi < 4; mi++) {
            int row = wm * 64 + mi * 16 + a_r;
            ldsm4(af[mi], ab + row * 128 + ((ch ^ (row & 7)) << 4));
        }
    };
    auto load_bfrag = [&](uint32_t bb, int kk, uint32_t bf[4][4]) {
        int ch = kk * 2 + b_cb;
        #pragma unroll
        for (int jp = 0; jp < 4; jp++) {
            int row = wn * 64 + jp * 16 + b_rr;
            ldsm4(bf[jp], bb + row * 128 + ((ch ^ (row & 7)) << 4));
        }
    };

    issue(0);
    issue(1);

    uint32_t af[2][4][4], bf[2][4][4];

    #pragma unroll 1
    for (int s = 0; s < NSTG; s++) {
        if (s == NSTG - 1) cp_wait<0>();
        else               cp_wait<1>();   // stage s landed
        __syncthreads();                   // data visible + slot (s-1)%3 free
        if (s + 2 < NSTG) issue(s + 2);    // prefetch 2 ahead into freed slot

        const uint32_t ab = sb + (s % NBUF) * STG_BYTES;
        const uint32_t bb = ab + A_STG;

        load_afrag(ab, 0, af[0]);
        load_bfrag(bb, 0, bf[0]);

        #pragma unroll
        for (int kk = 0; kk < 4; kk++) {
            const int cur = kk & 1;
            if (kk < 3) {
                load_afrag(ab, kk + 1, af[cur ^ 1]);
                load_bfrag(bb, kk + 1, bf[cur ^ 1]);
            }
            #pragma unroll
            for (int mi = 0; mi < 4; mi++)
                #pragma unroll
                for (int j = 0; j < 8; j++)
                    mma16816(acc[mi][j], af[cur][mi], &bf[cur][j >> 1][(j & 1) * 2]);
        }
    }

    // ---------------- epilogue ----------------
    const int q  = lane & 3;
    const int tr = lane >> 2;
    float kwv[8][2], bsv[8][2];
    #pragma unroll
    for (int j = 0; j < 8; j++) {
        int C = n0p + wn * 64 + 8 * j + 2 * q;
        float2 kw2 = *reinterpret_cast<const float2*>(&g_kwP[C]);
        float2 bs2 = *reinterpret_cast<const float2*>(&g_biasP[C]);
        kwv[j][0] = kw2.x; kwv[j][1] = kw2.y;
        bsv[j][0] = bs2.x; bsv[j][1] = bs2.y;
    }
    const int u0 = (blockIdx.y * 64) + wn * 16 + 4 * q;   // 4 consecutive units

    #pragma unroll
    for (int mi = 0; mi < 4; mi++) {
        #pragma unroll
        for (int h = 0; h < 2; h++) {
            int row = m0 + wm * 64 + mi * 16 + tr + 8 * h;
            float xb = xsrc ? xsrc[row * xstride] : g_pred[row];
            float4 cold = *reinterpret_cast<const float4*>(&g_c[row * 1024 + u0]);
            float co[4] = {cold.x, cold.y, cold.z, cold.w};
            float cn[4];
            __nv_bfloat16 hh_hi[4], hh_lo[4];
            #pragma unroll
            for (int jl = 0; jl < 4; jl++) {
                float zi = acc[mi][jl    ][2 * h    ] + xb * kwv[jl    ][0] + bsv[jl    ][0];
                float zf = acc[mi][jl    ][2 * h + 1] + xb * kwv[jl    ][1] + bsv[jl    ][1];
                float zg = acc[mi][jl + 4][2 * h    ] + xb * kwv[jl + 4][0] + bsv[jl + 4][0];
                float zo = acc[mi][jl + 4][2 * h + 1] + xb * kwv[jl + 4][1] + bsv[jl + 4][1];
                float ig = sigm(zi);
                float fg = sigm(zf);
                float gg = tanh_fast(zg);
                float og = sigm(zo);
                float cc = fg * co[jl] + ig * gg;
                cn[jl] = cc;
                float hh = og * tanh_fast(cc);
                __nv_bfloat16 hi = __float2bfloat16(hh);
                hh_hi[jl] = hi;
                hh_lo[jl] = __float2bfloat16(hh - __bfloat162float(hi));
            }
            float4 cv = {cn[0], cn[1], cn[2], cn[3]};
            *reinterpret_cast<float4*>(&g_c[row * 1024 + u0]) = cv;
            uint2 hv, lv;
            memcpy(&hv, hh_hi, 8);
            memcpy(&lv, hh_lo, 8);
            *reinterpret_cast<uint2*>(&Aout[row * 2048 + u0])        = hv;
            *reinterpret_cast<uint2*>(&Aout[row * 2048 + 1024 + u0]) = lv;
        }
    }
}

// ---------------- prediction head ----------------
__global__ void __launch_bounds__(256) pred_kernel(
    const float* __restrict__ w1, const float* __restrict__ b1,
    const float* __restrict__ w2, const float* __restrict__ b2,
    float* __restrict__ out, int tcol, int pin, int final_dense)
{
    int warp = (blockIdx.x * blockDim.x + threadIdx.x) >> 5;
    int lane = threadIdx.x & 31;
    if (warp >= BATCH) return;
    const __nv_bfloat16* __restrict__ ha = &g_A[pin][warp * 2048];
    float s = 0.0f;
    #pragma unroll 4
    for (int k = lane; k < UNITS; k += 32) {
        float h = __bfloat162float(ha[k]) + __bfloat162float(ha[1024 + k]);
        s = fmaf(h, w1[k], s);
    }
    #pragma unroll
    for (int off = 16; off; off >>= 1) s += __shfl_down_sync(0xffffffffu, s, off);
    if (lane == 0) {
        float x = fmaxf(s + b1[0], 0.0f);
        float p = final_dense ? fmaf(x, w2[0], b2[0]) : x;
        out[warp * OUT_STEPS + tcol] = p;
        g_pred[warp] = p;
    }
}

extern "C" void kernel_launch(void* const* d_in, const int* in_sizes, int n_in,
                              void* d_out, int out_size)
{
    const float* inputs = (const float*)d_in[0];
    const float* Kw     = (const float*)d_in[1];
    const float* R      = (const float*)d_in[2];
    const float* bias   = (const float*)d_in[3];
    const float* w1     = (const float*)d_in[4];
    const float* b1     = (const float*)d_in[5];
    const float* w2     = (const float*)d_in[6];
    const float* b2     = (const float*)d_in[7];
    float* out = (float*)d_out;

    cudaFuncSetAttribute(lstm_mma, cudaFuncAttributeMaxDynamicSharedMemorySize, SMEM_TOTAL);

    zero_kernel<<<(BATCH * UNITS + 255) / 256, 256>>>();
    prep_kernel<<<(4096 * 1024 + 255) / 256, 256>>>(R, Kw, bias);

    dim3 grid(BATCH / BM, 4096 / BN);   // (32, 16)
    int pp = 0;

    for (int t = 0; t < SEQ_LEN; t++) {
        lstm_mma<<<grid, 256, SMEM_TOTAL>>>(inputs + t, SEQ_LEN, pp);
        pp ^= 1;
    }
    pred_kernel<<<BATCH / 8, 256>>>(w1, b1, w2, b2, out, 0, pp, 0);

    for (int j = 1; j < OUT_STEPS; j++) {
        lstm_mma<<<grid, 256, SMEM_TOTAL>>>(nullptr, 1, pp);
        pp ^= 1;
        pred_kernel<<<BATCH / 8, 256>>>(w1, b1, w2, b2, out, j, pp, 1);
    }
}

// round 6
// speedup vs baseline: 2.2136x; 1.0731x over previous
#include <cuda_runtime.h>
#include <cuda_bf16.h>
#include <math.h>
#include <cstdint>

#define BATCH 4096
#define UNITS 1024
#define OUT_STEPS 200
#define SEQ_LEN 5

#define KTOT 3072        // [h_hi | h_hi | h_lo] x [R_hi ; R_lo ; R_hi]
#define BK 64
#define NSTG (KTOT / BK) // 48
#define BM 128
#define BN 256           // permuted z columns (= 64 units x 4 gates)
#define NTHREADS 512

#define A_STG (BM * BK * 2)             // 16KB
#define B_STG (BN * BK * 2)             // 32KB
#define STG_BYTES (A_STG + B_STG)       // 48KB
#define NBUF 3
#define SMEM_TOTAL (NBUF * STG_BYTES)   // 144KB

// ---------------- device globals ----------------
__device__ __nv_bfloat16 g_A[2][BATCH * 2048]; // ping-pong: [b][0:1024)=h_hi, [1024:2048)=h_lo
__device__ __nv_bfloat16 g_B[4096 * KTOT];     // permuted split R, row C, K-major
__device__ float g_c[BATCH * UNITS];
__device__ float g_pred[BATCH];
__device__ float g_kwP[4096];
__device__ float g_biasP[4096];

// ---------------- helpers ----------------
__device__ __forceinline__ uint32_t smem_u32(const void* p) {
    uint32_t a;
    asm("{ .reg .u64 t; cvta.to.shared.u64 t, %1; cvt.u32.u64 %0, t; }" : "=r"(a) : "l"(p));
    return a;
}
__device__ __forceinline__ void cp16(uint32_t saddr, const void* gaddr) {
    asm volatile("cp.async.cg.shared.global [%0], [%1], 16;" :: "r"(saddr), "l"(gaddr));
}
__device__ __forceinline__ void cp_commit() {
    asm volatile("cp.async.commit_group;" ::: "memory");
}
template<int N> __device__ __forceinline__ void cp_wait() {
    asm volatile("cp.async.wait_group %0;" :: "n"(N) : "memory");
}
__device__ __forceinline__ void ldsm4(uint32_t* r, uint32_t addr) {
    asm volatile("ldmatrix.sync.aligned.m8n8.x4.shared.b16 {%0,%1,%2,%3}, [%4];"
                 : "=r"(r[0]), "=r"(r[1]), "=r"(r[2]), "=r"(r[3]) : "r"(addr));
}
__device__ __forceinline__ void mma16816(float* c, const uint32_t* a, const uint32_t* b) {
    asm volatile(
        "mma.sync.aligned.m16n8k16.row.col.f32.bf16.bf16.f32 "
        "{%0,%1,%2,%3}, {%4,%5,%6,%7}, {%8,%9}, {%0,%1,%2,%3};"
        : "+f"(c[0]), "+f"(c[1]), "+f"(c[2]), "+f"(c[3])
        : "r"(a[0]), "r"(a[1]), "r"(a[2]), "r"(a[3]), "r"(b[0]), "r"(b[1]));
}
__device__ __forceinline__ float sigm(float x) { return 1.0f / (1.0f + __expf(-x)); }
__device__ __forceinline__ float tanh_fast(float x) {
    float t = __expf(-2.0f * fabsf(x));
    float r = (1.0f - t) / (1.0f + t);
    return copysignf(r, x);
}

// ---------------- prep: build permuted split-bf16 B ----------------
// Permuted column C <- (unit u, gate g):
//   C = (u>>4)*64 + (g>>1)*32 + (u&3)*8 + ((u>>2)&3)*2 + (g&1)
// Inverse: u = (C>>6)*16 + ((C>>1)&3)*4 + ((C>>3)&3) ; g = ((C>>5)&1)*2 + (C&1)
__global__ void prep_kernel(const float* __restrict__ R, const float* __restrict__ Kw,
                            const float* __restrict__ bias) {
    int idx = blockIdx.x * blockDim.x + threadIdx.x;   // np*1024 + k
    if (idx >= 4096 * 1024) return;
    int np = idx >> 10;
    int k  = idx & 1023;
    int u = ((np >> 6) << 4) | (((np >> 1) & 3) << 2) | ((np >> 3) & 3);
    int g = (((np >> 5) & 1) << 1) | (np & 1);
    int n = g * 1024 + u;
    float v = R[k * 4096 + n];
    __nv_bfloat16 hi = __float2bfloat16(v);
    __nv_bfloat16 lo = __float2bfloat16(v - __bfloat162float(hi));
    g_B[np * KTOT + k]        = hi;
    g_B[np * KTOT + 1024 + k] = lo;
    g_B[np * KTOT + 2048 + k] = hi;
    if (k == 0) { g_kwP[np] = Kw[n]; g_biasP[np] = bias[n]; }
}

__global__ void zero_kernel() {
    int i = blockIdx.x * blockDim.x + threadIdx.x;
    if (i < BATCH * UNITS) {
        ((uint32_t*)g_A[0])[i] = 0;   // 4M u32 = all 8M bf16 of g_A[0]
        g_c[i] = 0.0f;
    }
}

// ---------------- fused LSTM step (bf16 mma.sync GEMM + gates) ----------------
__global__ void __launch_bounds__(NTHREADS, 1) lstm_mma(const float* __restrict__ xsrc,
                                                        int xstride, int pin) {
    extern __shared__ char smem[];
    const uint32_t sb = smem_u32(smem);
    const int tid  = threadIdx.x;
    const int wid  = tid >> 5;
    const int lane = tid & 31;
    const int wm   = wid >> 2;       // 0..3 (32-row group)
    const int wn   = wid & 3;        // 0..3 (64-col group)
    const int m0   = blockIdx.x * BM;
    const int n0p  = blockIdx.y * BN;   // permuted-col base

    const __nv_bfloat16* __restrict__ Ain = g_A[pin];
    __nv_bfloat16* __restrict__ Aout = g_A[pin ^ 1];

    float acc[2][8][4];
    #pragma unroll
    for (int a = 0; a < 2; a++)
        #pragma unroll
        for (int b = 0; b < 8; b++)
            #pragma unroll
            for (int c = 0; c < 4; c++) acc[a][b][c] = 0.0f;

    const int cprow = tid >> 3;     // 0..63
    const int cpch  = tid & 7;

    auto issue = [&](int s) {
        const int buf = s % NBUF;
        const int kA = (s & 15) * BK + ((s >= 32) ? 1024 : 0);
        const int kB = s * BK;
        const uint32_t ab = sb + buf * STG_BYTES;
        const uint32_t bb = ab + A_STG;
        #pragma unroll
        for (int p = 0; p < 2; p++) {                 // A: 128 rows
            int row = cprow + p * 64;
            uint32_t sa = ab + row * 128 + ((cpch ^ (row & 7)) << 4);
            cp16(sa, &Ain[(m0 + row) * 2048 + kA + cpch * 8]);
        }
        #pragma unroll
        for (int p = 0; p < 4; p++) {                 // B: 256 rows
            int row = cprow + p * 64;
            uint32_t sa = bb + row * 128 + ((cpch ^ (row & 7)) << 4);
            cp16(sa, &g_B[(uint64_t)(n0p + row) * KTOT + kB + cpch * 8]);
        }
        cp_commit();
    };

    // fragment lane mapping
    const int a_r  = lane & 15;
    const int a_cb = lane >> 4;
    const int b_rr = (lane & 7) + ((lane >> 4) << 3);
    const int b_cb = (lane >> 3) & 1;

    issue(0);
    issue(1);

    #pragma unroll 1
    for (int s = 0; s < NSTG; s++) {
        if (s == NSTG - 1) cp_wait<0>();
        else               cp_wait<1>();   // stage s landed
        __syncthreads();                   // data visible + slot (s-1)%NBUF free
        if (s + 2 < NSTG) issue(s + 2);    // prefetch 2 ahead into freed slot

        const uint32_t ab = sb + (s % NBUF) * STG_BYTES;
        const uint32_t bb = ab + A_STG;

        #pragma unroll
        for (int kk = 0; kk < 4; kk++) {
            uint32_t af[2][4], bf[4][4];
            {
                int ch = kk * 2 + a_cb;
                #pragma unroll
                for (int mi = 0; mi < 2; mi++) {
                    int row = wm * 32 + mi * 16 + a_r;
                    ldsm4(af[mi], ab + row * 128 + ((ch ^ (row & 7)) << 4));
                }
            }
            {
                int ch = kk * 2 + b_cb;
                #pragma unroll
                for (int jp = 0; jp < 4; jp++) {
                    int row = wn * 64 + jp * 16 + b_rr;
                    ldsm4(bf[jp], bb + row * 128 + ((ch ^ (row & 7)) << 4));
                }
            }
            #pragma unroll
            for (int mi = 0; mi < 2; mi++)
                #pragma unroll
                for (int j = 0; j < 8; j++)
                    mma16816(acc[mi][j], af[mi], &bf[j >> 1][(j & 1) * 2]);
        }
    }

    // ---------------- epilogue ----------------
    const int q  = lane & 3;
    const int tr = lane >> 2;
    float kwv[8][2], bsv[8][2];
    #pragma unroll
    for (int j = 0; j < 8; j++) {
        int C = n0p + wn * 64 + 8 * j + 2 * q;
        float2 kw2 = *reinterpret_cast<const float2*>(&g_kwP[C]);
        float2 bs2 = *reinterpret_cast<const float2*>(&g_biasP[C]);
        kwv[j][0] = kw2.x; kwv[j][1] = kw2.y;
        bsv[j][0] = bs2.x; bsv[j][1] = bs2.y;
    }
    const int u0 = (blockIdx.y * 64) + wn * 16 + 4 * q;   // 4 consecutive units

    #pragma unroll
    for (int mi = 0; mi < 2; mi++) {
        #pragma unroll
        for (int h = 0; h < 2; h++) {
            int row = m0 + wm * 32 + mi * 16 + tr + 8 * h;
            float xb = xsrc ? xsrc[row * xstride] : g_pred[row];
            float4 cold = *reinterpret_cast<const float4*>(&g_c[row * 1024 + u0]);
            float co[4] = {cold.x, cold.y, cold.z, cold.w};
            float cn[4];
            __nv_bfloat16 hh_hi[4], hh_lo[4];
            #pragma unroll
            for (int jl = 0; jl < 4; jl++) {
                float zi = acc[mi][jl    ][2 * h    ] + xb * kwv[jl    ][0] + bsv[jl    ][0];
                float zf = acc[mi][jl    ][2 * h + 1] + xb * kwv[jl    ][1] + bsv[jl    ][1];
                float zg = acc[mi][jl + 4][2 * h    ] + xb * kwv[jl + 4][0] + bsv[jl + 4][0];
                float zo = acc[mi][jl + 4][2 * h + 1] + xb * kwv[jl + 4][1] + bsv[jl + 4][1];
                float ig = sigm(zi);
                float fg = sigm(zf);
                float gg = tanh_fast(zg);
                float og = sigm(zo);
                float cc = fg * co[jl] + ig * gg;
                cn[jl] = cc;
                float hh = og * tanh_fast(cc);
                __nv_bfloat16 hi = __float2bfloat16(hh);
                hh_hi[jl] = hi;
                hh_lo[jl] = __float2bfloat16(hh - __bfloat162float(hi));
            }
            float4 cv = {cn[0], cn[1], cn[2], cn[3]};
            *reinterpret_cast<float4*>(&g_c[row * 1024 + u0]) = cv;
            uint2 hv, lv;
            memcpy(&hv, hh_hi, 8);
            memcpy(&lv, hh_lo, 8);
            *reinterpret_cast<uint2*>(&Aout[row * 2048 + u0])        = hv;
            *reinterpret_cast<uint2*>(&Aout[row * 2048 + 1024 + u0]) = lv;
        }
    }
}

// ---------------- prediction head ----------------
__global__ void __launch_bounds__(256) pred_kernel(
    const float* __restrict__ w1, const float* __restrict__ b1,
    const float* __restrict__ w2, const float* __restrict__ b2,
    float* __restrict__ out, int tcol, int pin, int final_dense)
{
    int warp = (blockIdx.x * blockDim.x + threadIdx.x) >> 5;
    int lane = threadIdx.x & 31;
    if (warp >= BATCH) return;
    const __nv_bfloat16* __restrict__ ha = &g_A[pin][warp * 2048];
    float s = 0.0f;
    #pragma unroll 4
    for (int k = lane; k < UNITS; k += 32) {
        float h = __bfloat162float(ha[k]) + __bfloat162float(ha[1024 + k]);
        s = fmaf(h, w1[k], s);
    }
    #pragma unroll
    for (int off = 16; off; off >>= 1) s += __shfl_down_sync(0xffffffffu, s, off);
    if (lane == 0) {
        float x = fmaxf(s + b1[0], 0.0f);
        float p = final_dense ? fmaf(x, w2[0], b2[0]) : x;
        out[warp * OUT_STEPS + tcol] = p;
        g_pred[warp] = p;
    }
}

extern "C" void kernel_launch(void* const* d_in, const int* in_sizes, int n_in,
                              void* d_out, int out_size)
{
    const float* inputs = (const float*)d_in[0];
    const float* Kw     = (const float*)d_in[1];
    const float* R      = (const float*)d_in[2];
    const float* bias   = (const float*)d_in[3];
    const float* w1     = (const float*)d_in[4];
    const float* b1     = (const float*)d_in[5];
    const float* w2     = (const float*)d_in[6];
    const float* b2     = (const float*)d_in[7];
    float* out = (float*)d_out;

    cudaFuncSetAttribute(lstm_mma, cudaFuncAttributeMaxDynamicSharedMemorySize, SMEM_TOTAL);

    zero_kernel<<<(BATCH * UNITS + 255) / 256, 256>>>();
    prep_kernel<<<(4096 * 1024 + 255) / 256, 256>>>(R, Kw, bias);

    dim3 grid(BATCH / BM, 4096 / BN);   // (32, 16)
    int pp = 0;

    for (int t = 0; t < SEQ_LEN; t++) {
        lstm_mma<<<grid, NTHREADS, SMEM_TOTAL>>>(inputs + t, SEQ_LEN, pp);
        pp ^= 1;
    }
    pred_kernel<<<BATCH / 8, 256>>>(w1, b1, w2, b2, out, 0, pp, 0);

    for (int j = 1; j < OUT_STEPS; j++) {
        lstm_mma<<<grid, NTHREADS, SMEM_TOTAL>>>(nullptr, 1, pp);
        pp ^= 1;
        pred_kernel<<<BATCH / 8, 256>>>(w1, b1, w2, b2, out, j, pp, 1);
    }
}

// round 7
// speedup vs baseline: 2.8055x; 1.2674x over previous
#include <cuda_runtime.h>
#include <cuda_bf16.h>
#include <math.h>
#include <cstdint>

#define BATCH 4096
#define UNITS 1024
#define OUT_STEPS 200
#define SEQ_LEN 5

#define KTOT 3072        // [h_hi | h_hi | h_lo] x [R_hi ; R_lo ; R_hi]
#define BK 64
#define NSTG (KTOT / BK) // 48
#define BM 128
#define BN 128           // permuted z columns (= 32 units x 4 gates)
#define NTHREADS 256

#define A_STG (BM * BK * 2)             // 16KB
#define B_STG (BN * BK * 2)             // 16KB
#define STG_BYTES (A_STG + B_STG)       // 32KB
#define NBUF 3
#define SMEM_TOTAL (NBUF * STG_BYTES)   // 96KB -> 2 CTAs/SM

// ---------------- device globals ----------------
__device__ __nv_bfloat16 g_A[2][BATCH * 2048]; // ping-pong: [b][0:1024)=h_hi, [1024:2048)=h_lo
__device__ __nv_bfloat16 g_B[4096 * KTOT];     // permuted split R, row C, K-major
__device__ float g_c[BATCH * UNITS];
__device__ float g_pred[BATCH];
__device__ float g_kwP[4096];
__device__ float g_biasP[4096];

// ---------------- helpers ----------------
__device__ __forceinline__ uint32_t smem_u32(const void* p) {
    uint32_t a;
    asm("{ .reg .u64 t; cvta.to.shared.u64 t, %1; cvt.u32.u64 %0, t; }" : "=r"(a) : "l"(p));
    return a;
}
__device__ __forceinline__ void cp16(uint32_t saddr, const void* gaddr) {
    asm volatile("cp.async.cg.shared.global [%0], [%1], 16;" :: "r"(saddr), "l"(gaddr));
}
__device__ __forceinline__ void cp_commit() {
    asm volatile("cp.async.commit_group;" ::: "memory");
}
template<int N> __device__ __forceinline__ void cp_wait() {
    asm volatile("cp.async.wait_group %0;" :: "n"(N) : "memory");
}
__device__ __forceinline__ void ldsm4(uint32_t* r, uint32_t addr) {
    asm volatile("ldmatrix.sync.aligned.m8n8.x4.shared.b16 {%0,%1,%2,%3}, [%4];"
                 : "=r"(r[0]), "=r"(r[1]), "=r"(r[2]), "=r"(r[3]) : "r"(addr));
}
__device__ __forceinline__ void mma16816(float* c, const uint32_t* a, const uint32_t* b) {
    asm volatile(
        "mma.sync.aligned.m16n8k16.row.col.f32.bf16.bf16.f32 "
        "{%0,%1,%2,%3}, {%4,%5,%6,%7}, {%8,%9}, {%0,%1,%2,%3};"
        : "+f"(c[0]), "+f"(c[1]), "+f"(c[2]), "+f"(c[3])
        : "r"(a[0]), "r"(a[1]), "r"(a[2]), "r"(a[3]), "r"(b[0]), "r"(b[1]));
}
__device__ __forceinline__ float sigm(float x) { return 1.0f / (1.0f + __expf(-x)); }
__device__ __forceinline__ float tanh_fast(float x) {
    float t = __expf(-2.0f * fabsf(x));
    float r = (1.0f - t) / (1.0f + t);
    return copysignf(r, x);
}

// ---------------- prep: build permuted split-bf16 B ----------------
// Permuted column C <- (unit u, gate g):
//   C = (u>>4)*64 + (g>>1)*32 + (u&3)*8 + ((u>>2)&3)*2 + (g&1)
// Inverse: u = (C>>6)*16 + ((C>>1)&3)*4 + ((C>>3)&3) ; g = ((C>>5)&1)*2 + (C&1)
__global__ void prep_kernel(const float* __restrict__ R, const float* __restrict__ Kw,
                            const float* __restrict__ bias) {
    int idx = blockIdx.x * blockDim.x + threadIdx.x;   // np*1024 + k
    if (idx >= 4096 * 1024) return;
    int np = idx >> 10;
    int k  = idx & 1023;
    int u = ((np >> 6) << 4) | (((np >> 1) & 3) << 2) | ((np >> 3) & 3);
    int g = (((np >> 5) & 1) << 1) | (np & 1);
    int n = g * 1024 + u;
    float v = R[k * 4096 + n];
    __nv_bfloat16 hi = __float2bfloat16(v);
    __nv_bfloat16 lo = __float2bfloat16(v - __bfloat162float(hi));
    g_B[np * KTOT + k]        = hi;
    g_B[np * KTOT + 1024 + k] = lo;
    g_B[np * KTOT + 2048 + k] = hi;
    if (k == 0) { g_kwP[np] = Kw[n]; g_biasP[np] = bias[n]; }
}

__global__ void zero_kernel() {
    int i = blockIdx.x * blockDim.x + threadIdx.x;
    if (i < BATCH * UNITS) {
        ((uint32_t*)g_A[0])[i] = 0;   // 4M u32 = all 8M bf16 of g_A[0]
        g_c[i] = 0.0f;
    }
}

// ---------------- fused LSTM step (bf16 mma.sync GEMM + gates) ----------------
__global__ void __launch_bounds__(NTHREADS, 2) lstm_mma(const float* __restrict__ xsrc,
                                                        int xstride, int pin) {
    extern __shared__ char smem[];
    const uint32_t sb = smem_u32(smem);
    const int tid  = threadIdx.x;
    const int wid  = tid >> 5;
    const int lane = tid & 31;
    const int wm   = wid >> 1;       // 0..3 (32-row group)
    const int wn   = wid & 1;        // 0..1 (64-col group)
    const int krot = wid & 3;        // kk-phase rotation per warp
    const int m0   = blockIdx.x * BM;
    const int n0p  = blockIdx.y * BN;   // permuted-col base

    const __nv_bfloat16* __restrict__ Ain = g_A[pin];
    __nv_bfloat16* __restrict__ Aout = g_A[pin ^ 1];

    float acc[2][8][4];
    #pragma unroll
    for (int a = 0; a < 2; a++)
        #pragma unroll
        for (int b = 0; b < 8; b++)
            #pragma unroll
            for (int c = 0; c < 4; c++) acc[a][b][c] = 0.0f;

    const int cprow = tid >> 3;     // 0..31
    const int cpch  = tid & 7;

    auto issue = [&](int s) {
        const int buf = s % NBUF;
        const int kA = (s & 15) * BK + ((s >= 32) ? 1024 : 0);
        const int kB = s * BK;
        const uint32_t ab = sb + buf * STG_BYTES;
        const uint32_t bb = ab + A_STG;
        #pragma unroll
        for (int p = 0; p < 4; p++) {                 // A: 128 rows
            int row = cprow + p * 32;
            uint32_t sa = ab + row * 128 + ((cpch ^ (row & 7)) << 4);
            cp16(sa, &Ain[(m0 + row) * 2048 + kA + cpch * 8]);
        }
        #pragma unroll
        for (int p = 0; p < 4; p++) {                 // B: 128 rows
            int row = cprow + p * 32;
            uint32_t sa = bb + row * 128 + ((cpch ^ (row & 7)) << 4);
            cp16(sa, &g_B[(uint64_t)(n0p + row) * KTOT + kB + cpch * 8]);
        }
        cp_commit();
    };

    // fragment lane mapping
    const int a_r  = lane & 15;
    const int a_cb = lane >> 4;
    const int b_rr = (lane & 7) + ((lane >> 4) << 3);
    const int b_cb = (lane >> 3) & 1;

    issue(0);
    issue(1);

    #pragma unroll 1
    for (int s = 0; s < NSTG; s++) {
        if (s == NSTG - 1) cp_wait<0>();
        else               cp_wait<1>();   // stage s landed
        __syncthreads();                   // data visible + slot (s-1)%NBUF free
        if (s + 2 < NSTG) issue(s + 2);    // prefetch 2 ahead into freed slot

        const uint32_t ab = sb + (s % NBUF) * STG_BYTES;
        const uint32_t bb = ab + A_STG;

        #pragma unroll
        for (int kk = 0; kk < 4; kk++) {
            const int kq = (kk + krot) & 3;   // per-warp phase rotation
            uint32_t af[2][4], bf[4][4];
            {
                int ch = kq * 2 + a_cb;
                #pragma unroll
                for (int mi = 0; mi < 2; mi++) {
                    int row = wm * 32 + mi * 16 + a_r;
                    ldsm4(af[mi], ab + row * 128 + ((ch ^ (row & 7)) << 4));
                }
            }
            {
                int ch = kq * 2 + b_cb;
                #pragma unroll
                for (int jp = 0; jp < 4; jp++) {
                    int row = wn * 64 + jp * 16 + b_rr;
                    ldsm4(bf[jp], bb + row * 128 + ((ch ^ (row & 7)) << 4));
                }
            }
            #pragma unroll
            for (int mi = 0; mi < 2; mi++)
                #pragma unroll
                for (int j = 0; j < 8; j++)
                    mma16816(acc[mi][j], af[mi], &bf[j >> 1][(j & 1) * 2]);
        }
    }

    // ---------------- epilogue ----------------
    const int q  = lane & 3;
    const int tr = lane >> 2;
    float kwv[8][2], bsv[8][2];
    #pragma unroll
    for (int j = 0; j < 8; j++) {
        int C = n0p + wn * 64 + 8 * j + 2 * q;
        float2 kw2 = *reinterpret_cast<const float2*>(&g_kwP[C]);
        float2 bs2 = *reinterpret_cast<const float2*>(&g_biasP[C]);
        kwv[j][0] = kw2.x; kwv[j][1] = kw2.y;
        bsv[j][0] = bs2.x; bsv[j][1] = bs2.y;
    }
    // global 64-col-group index = blockIdx.y*2 + wn; 16 units per group
    const int u0 = (blockIdx.y * 2 + wn) * 16 + 4 * q;   // 4 consecutive units

    #pragma unroll
    for (int mi = 0; mi < 2; mi++) {
        #pragma unroll
        for (int h = 0; h < 2; h++) {
            int row = m0 + wm * 32 + mi * 16 + tr + 8 * h;
            float xb = xsrc ? xsrc[row * xstride] : g_pred[row];
            float4 cold = *reinterpret_cast<const float4*>(&g_c[row * 1024 + u0]);
            float co[4] = {cold.x, cold.y, cold.z, cold.w};
            float cn[4];
            __nv_bfloat16 hh_hi[4], hh_lo[4];
            #pragma unroll
            for (int jl = 0; jl < 4; jl++) {
                float zi = acc[mi][jl    ][2 * h    ] + xb * kwv[jl    ][0] + bsv[jl    ][0];
                float zf = acc[mi][jl    ][2 * h + 1] + xb * kwv[jl    ][1] + bsv[jl    ][1];
                float zg = acc[mi][jl + 4][2 * h    ] + xb * kwv[jl + 4][0] + bsv[jl + 4][0];
                float zo = acc[mi][jl + 4][2 * h + 1] + xb * kwv[jl + 4][1] + bsv[jl + 4][1];
                float ig = sigm(zi);
                float fg = sigm(zf);
                float gg = tanh_fast(zg);
                float og = sigm(zo);
                float cc = fg * co[jl] + ig * gg;
                cn[jl] = cc;
                float hh = og * tanh_fast(cc);
                __nv_bfloat16 hi = __float2bfloat16(hh);
                hh_hi[jl] = hi;
                hh_lo[jl] = __float2bfloat16(hh - __bfloat162float(hi));
            }
            float4 cv = {cn[0], cn[1], cn[2], cn[3]};
            *reinterpret_cast<float4*>(&g_c[row * 1024 + u0]) = cv;
            uint2 hv, lv;
            memcpy(&hv, hh_hi, 8);
            memcpy(&lv, hh_lo, 8);
            *reinterpret_cast<uint2*>(&Aout[row * 2048 + u0])        = hv;
            *reinterpret_cast<uint2*>(&Aout[row * 2048 + 1024 + u0]) = lv;
        }
    }
}

// ---------------- prediction head ----------------
__global__ void __launch_bounds__(256) pred_kernel(
    const float* __restrict__ w1, const float* __restrict__ b1,
    const float* __restrict__ w2, const float* __restrict__ b2,
    float* __restrict__ out, int tcol, int pin, int final_dense)
{
    int warp = (blockIdx.x * blockDim.x + threadIdx.x) >> 5;
    int lane = threadIdx.x & 31;
    if (warp >= BATCH) return;
    const __nv_bfloat16* __restrict__ ha = &g_A[pin][warp * 2048];
    float s = 0.0f;
    #pragma unroll 4
    for (int k = lane; k < UNITS; k += 32) {
        float h = __bfloat162float(ha[k]) + __bfloat162float(ha[1024 + k]);
        s = fmaf(h, w1[k], s);
    }
    #pragma unroll
    for (int off = 16; off; off >>= 1) s += __shfl_down_sync(0xffffffffu, s, off);
    if (lane == 0) {
        float x = fmaxf(s + b1[0], 0.0f);
        float p = final_dense ? fmaf(x, w2[0], b2[0]) : x;
        out[warp * OUT_STEPS + tcol] = p;
        g_pred[warp] = p;
    }
}

extern "C" void kernel_launch(void* const* d_in, const int* in_sizes, int n_in,
                              void* d_out, int out_size)
{
    const float* inputs = (const float*)d_in[0];
    const float* Kw     = (const float*)d_in[1];
    const float* R      = (const float*)d_in[2];
    const float* bias   = (const float*)d_in[3];
    const float* w1     = (const float*)d_in[4];
    const float* b1     = (const float*)d_in[5];
    const float* w2     = (const float*)d_in[6];
    const float* b2     = (const float*)d_in[7];
    float* out = (float*)d_out;

    cudaFuncSetAttribute(lstm_mma, cudaFuncAttributeMaxDynamicSharedMemorySize, SMEM_TOTAL);

    zero_kernel<<<(BATCH * UNITS + 255) / 256, 256>>>();
    prep_kernel<<<(4096 * 1024 + 255) / 256, 256>>>(R, Kw, bias);

    dim3 grid(BATCH / BM, 4096 / BN);   // (32, 32)
    int pp = 0;

    for (int t = 0; t < SEQ_LEN; t++) {
        lstm_mma<<<grid, NTHREADS, SMEM_TOTAL>>>(inputs + t, SEQ_LEN, pp);
        pp ^= 1;
    }
    pred_kernel<<<BATCH / 8, 256>>>(w1, b1, w2, b2, out, 0, pp, 0);

    for (int j = 1; j < OUT_STEPS; j++) {
        lstm_mma<<<grid, NTHREADS, SMEM_TOTAL>>>(nullptr, 1, pp);
        pp ^= 1;
        pred_kernel<<<BATCH / 8, 256>>>(w1, b1, w2, b2, out, j, pp, 1);
    }
}

// round 8
// speedup vs baseline: 4.0785x; 1.4538x over previous
#include <cuda_runtime.h>
#include <cuda_fp16.h>
#include <math.h>
#include <cstdint>

#define BATCH 4096
#define UNITS 1024
#define OUT_STEPS 200
#define SEQ_LEN 5

#define KTOT 2048        // [h_hi | h_hi] x [R_hi ; R_lo], fp16
#define BK 64
#define NSTG (KTOT / BK) // 32
#define BM 128
#define BN 128           // permuted z columns (= 32 units x 4 gates)
#define NTHREADS 256

#define A_STG (BM * BK * 2)             // 16KB
#define B_STG (BN * BK * 2)             // 16KB
#define STG_BYTES (A_STG + B_STG)       // 32KB
#define NBUF 3
#define SMEM_TOTAL (NBUF * STG_BYTES)   // 96KB -> 2 CTAs/SM

// ---------------- device globals ----------------
__device__ __half g_A[2][BATCH * 1024];   // ping-pong hidden state, fp16
__device__ __half g_B[4096 * KTOT];       // permuted split R: row C, [R_hi(1024) | R_lo(1024)]
__device__ float g_c[BATCH * UNITS];
__device__ float g_pred[BATCH];
__device__ float g_kwP[4096];
__device__ float g_biasP[4096];

// ---------------- helpers ----------------
__device__ __forceinline__ uint32_t smem_u32(const void* p) {
    uint32_t a;
    asm("{ .reg .u64 t; cvta.to.shared.u64 t, %1; cvt.u32.u64 %0, t; }" : "=r"(a) : "l"(p));
    return a;
}
__device__ __forceinline__ void cp16(uint32_t saddr, const void* gaddr) {
    asm volatile("cp.async.cg.shared.global [%0], [%1], 16;" :: "r"(saddr), "l"(gaddr));
}
__device__ __forceinline__ void cp_commit() {
    asm volatile("cp.async.commit_group;" ::: "memory");
}
template<int N> __device__ __forceinline__ void cp_wait() {
    asm volatile("cp.async.wait_group %0;" :: "n"(N) : "memory");
}
__device__ __forceinline__ void ldsm4(uint32_t* r, uint32_t addr) {
    asm volatile("ldmatrix.sync.aligned.m8n8.x4.shared.b16 {%0,%1,%2,%3}, [%4];"
                 : "=r"(r[0]), "=r"(r[1]), "=r"(r[2]), "=r"(r[3]) : "r"(addr));
}
__device__ __forceinline__ void mma16816(float* c, const uint32_t* a, const uint32_t* b) {
    asm volatile(
        "mma.sync.aligned.m16n8k16.row.col.f32.f16.f16.f32 "
        "{%0,%1,%2,%3}, {%4,%5,%6,%7}, {%8,%9}, {%0,%1,%2,%3};"
        : "+f"(c[0]), "+f"(c[1]), "+f"(c[2]), "+f"(c[3])
        : "r"(a[0]), "r"(a[1]), "r"(a[2]), "r"(a[3]), "r"(b[0]), "r"(b[1]));
}
__device__ __forceinline__ float sigm(float x) { return 1.0f / (1.0f + __expf(-x)); }
__device__ __forceinline__ float tanh_fast(float x) {
    float t = __expf(-2.0f * fabsf(x));
    float r = (1.0f - t) / (1.0f + t);
    return copysignf(r, x);
}

// ---------------- prep: build permuted split-fp16 B ----------------
// Permuted column C <- (unit u, gate g):
//   C = (u>>4)*64 + (g>>1)*32 + (u&3)*8 + ((u>>2)&3)*2 + (g&1)
// Inverse: u = (C>>6)*16 + ((C>>1)&3)*4 + ((C>>3)&3) ; g = ((C>>5)&1)*2 + (C&1)
__global__ void prep_kernel(const float* __restrict__ R, const float* __restrict__ Kw,
                            const float* __restrict__ bias) {
    int idx = blockIdx.x * blockDim.x + threadIdx.x;   // np*1024 + k
    if (idx >= 4096 * 1024) return;
    int np = idx >> 10;
    int k  = idx & 1023;
    int u = ((np >> 6) << 4) | (((np >> 1) & 3) << 2) | ((np >> 3) & 3);
    int g = (((np >> 5) & 1) << 1) | (np & 1);
    int n = g * 1024 + u;
    float v = R[k * 4096 + n];
    __half hi = __float2half_rn(v);
    __half lo = __float2half_rn(v - __half2float(hi));
    g_B[np * KTOT + k]        = hi;
    g_B[np * KTOT + 1024 + k] = lo;
    if (k == 0) { g_kwP[np] = Kw[n]; g_biasP[np] = bias[n]; }
}

__global__ void zero_kernel() {
    int i = blockIdx.x * blockDim.x + threadIdx.x;
    if (i < BATCH * UNITS) {
        g_c[i] = 0.0f;
        if (i < BATCH * 512) ((uint32_t*)g_A[0])[i] = 0;   // 2M halfs
    }
}

// ---------------- fused LSTM step (fp16 mma.sync GEMM + gates) ----------------
__global__ void __launch_bounds__(NTHREADS, 2) lstm_mma(const float* __restrict__ xsrc,
                                                        int xstride, int pin) {
    extern __shared__ char smem[];
    const uint32_t sb = smem_u32(smem);
    const int tid  = threadIdx.x;
    const int wid  = tid >> 5;
    const int lane = tid & 31;
    const int wm   = wid >> 1;       // 0..3 (32-row group)
    const int wn   = wid & 1;        // 0..1 (64-col group)
    const int krot = wid & 3;        // kk-phase rotation per warp
    const int m0   = blockIdx.x * BM;
    const int n0p  = blockIdx.y * BN;   // permuted-col base

    const __half* __restrict__ Ain = g_A[pin];
    __half* __restrict__ Aout = g_A[pin ^ 1];

    float acc[2][8][4];
    #pragma unroll
    for (int a = 0; a < 2; a++)
        #pragma unroll
        for (int b = 0; b < 8; b++)
            #pragma unroll
            for (int c = 0; c < 4; c++) acc[a][b][c] = 0.0f;

    const int cprow = tid >> 3;     // 0..31
    const int cpch  = tid & 7;

    auto issue = [&](int s) {
        const int buf = s % NBUF;
        const int kA = (s & 15) * BK;      // h_hi repeated for s>=16
        const int kB = s * BK;
        const uint32_t ab = sb + buf * STG_BYTES;
        const uint32_t bb = ab + A_STG;
        #pragma unroll
        for (int p = 0; p < 4; p++) {                 // A: 128 rows
            int row = cprow + p * 32;
            uint32_t sa = ab + row * 128 + ((cpch ^ (row & 7)) << 4);
            cp16(sa, &Ain[(m0 + row) * 1024 + kA + cpch * 8]);
        }
        #pragma unroll
        for (int p = 0; p < 4; p++) {                 // B: 128 rows
            int row = cprow + p * 32;
            uint32_t sa = bb + row * 128 + ((cpch ^ (row & 7)) << 4);
            cp16(sa, &g_B[(uint64_t)(n0p + row) * KTOT + kB + cpch * 8]);
        }
        cp_commit();
    };

    // fragment lane mapping
    const int a_r  = lane & 15;
    const int a_cb = lane >> 4;
    const int b_rr = (lane & 7) + ((lane >> 4) << 3);
    const int b_cb = (lane >> 3) & 1;

    issue(0);
    issue(1);

    #pragma unroll 1
    for (int s = 0; s < NSTG; s++) {
        if (s == NSTG - 1) cp_wait<0>();
        else               cp_wait<1>();   // stage s landed
        __syncthreads();                   // data visible + slot (s-1)%NBUF free
        if (s + 2 < NSTG) issue(s + 2);    // prefetch 2 ahead into freed slot

        const uint32_t ab = sb + (s % NBUF) * STG_BYTES;
        const uint32_t bb = ab + A_STG;

        #pragma unroll
        for (int kk = 0; kk < 4; kk++) {
            const int kq = (kk + krot) & 3;   // per-warp phase rotation
            uint32_t af[2][4], bf[4][4];
            {
                int ch = kq * 2 + a_cb;
                #pragma unroll
                for (int mi = 0; mi < 2; mi++) {
                    int row = wm * 32 + mi * 16 + a_r;
                    ldsm4(af[mi], ab + row * 128 + ((ch ^ (row & 7)) << 4));
                }
            }
            {
                int ch = kq * 2 + b_cb;
                #pragma unroll
                for (int jp = 0; jp < 4; jp++) {
                    int row = wn * 64 + jp * 16 + b_rr;
                    ldsm4(bf[jp], bb + row * 128 + ((ch ^ (row & 7)) << 4));
                }
            }
            #pragma unroll
            for (int mi = 0; mi < 2; mi++)
                #pragma unroll
                for (int j = 0; j < 8; j++)
                    mma16816(acc[mi][j], af[mi], &bf[j >> 1][(j & 1) * 2]);
        }
    }

    // ---------------- epilogue ----------------
    const int q  = lane & 3;
    const int tr = lane >> 2;
    float kwv[8][2], bsv[8][2];
    #pragma unroll
    for (int j = 0; j < 8; j++) {
        int C = n0p + wn * 64 + 8 * j + 2 * q;
        float2 kw2 = *reinterpret_cast<const float2*>(&g_kwP[C]);
        float2 bs2 = *reinterpret_cast<const float2*>(&g_biasP[C]);
        kwv[j][0] = kw2.x; kwv[j][1] = kw2.y;
        bsv[j][0] = bs2.x; bsv[j][1] = bs2.y;
    }
    // global 64-col-group index = blockIdx.y*2 + wn; 16 units per group
    const int u0 = (blockIdx.y * 2 + wn) * 16 + 4 * q;   // 4 consecutive units

    #pragma unroll
    for (int mi = 0; mi < 2; mi++) {
        #pragma unroll
        for (int h = 0; h < 2; h++) {
            int row = m0 + wm * 32 + mi * 16 + tr + 8 * h;
            float xb = xsrc ? xsrc[row * xstride] : g_pred[row];
            float4 cold = *reinterpret_cast<const float4*>(&g_c[row * 1024 + u0]);
            float co[4] = {cold.x, cold.y, cold.z, cold.w};
            float cn[4];
            __half hh4[4];
            #pragma unroll
            for (int jl = 0; jl < 4; jl++) {
                float zi = acc[mi][jl    ][2 * h    ] + xb * kwv[jl    ][0] + bsv[jl    ][0];
                float zf = acc[mi][jl    ][2 * h + 1] + xb * kwv[jl    ][1] + bsv[jl    ][1];
                float zg = acc[mi][jl + 4][2 * h    ] + xb * kwv[jl + 4][0] + bsv[jl + 4][0];
                float zo = acc[mi][jl + 4][2 * h + 1] + xb * kwv[jl + 4][1] + bsv[jl + 4][1];
                float ig = sigm(zi);
                float fg = sigm(zf);
                float gg = tanh_fast(zg);
                float og = sigm(zo);
                float cc = fg * co[jl] + ig * gg;
                cn[jl] = cc;
                float hh = og * tanh_fast(cc);
                hh4[jl] = __float2half_rn(hh);
            }
            float4 cv = {cn[0], cn[1], cn[2], cn[3]};
            *reinterpret_cast<float4*>(&g_c[row * 1024 + u0]) = cv;
            uint2 hv;
            memcpy(&hv, hh4, 8);
            *reinterpret_cast<uint2*>(&Aout[row * 1024 + u0]) = hv;
        }
    }
}

// ---------------- prediction head ----------------
__global__ void __launch_bounds__(256) pred_kernel(
    const float* __restrict__ w1, const float* __restrict__ b1,
    const float* __restrict__ w2, const float* __restrict__ b2,
    float* __restrict__ out, int tcol, int pin, int final_dense)
{
    int warp = (blockIdx.x * blockDim.x + threadIdx.x) >> 5;
    int lane = threadIdx.x & 31;
    if (warp >= BATCH) return;
    const __half* __restrict__ ha = &g_A[pin][warp * 1024];
    float s = 0.0f;
    #pragma unroll 4
    for (int k = lane; k < UNITS; k += 32)
        s = fmaf(__half2float(ha[k]), w1[k], s);
    #pragma unroll
    for (int off = 16; off; off >>= 1) s += __shfl_down_sync(0xffffffffu, s, off);
    if (lane == 0) {
        float x = fmaxf(s + b1[0], 0.0f);
        float p = final_dense ? fmaf(x, w2[0], b2[0]) : x;
        out[warp * OUT_STEPS + tcol] = p;
        g_pred[warp] = p;
    }
}

extern "C" void kernel_launch(void* const* d_in, const int* in_sizes, int n_in,
                              void* d_out, int out_size)
{
    const float* inputs = (const float*)d_in[0];
    const float* Kw     = (const float*)d_in[1];
    const float* R      = (const float*)d_in[2];
    const float* bias   = (const float*)d_in[3];
    const float* w1     = (const float*)d_in[4];
    const float* b1     = (const float*)d_in[5];
    const float* w2     = (const float*)d_in[6];
    const float* b2     = (const float*)d_in[7];
    float* out = (float*)d_out;

    cudaFuncSetAttribute(lstm_mma, cudaFuncAttributeMaxDynamicSharedMemorySize, SMEM_TOTAL);

    zero_kernel<<<(BATCH * UNITS + 255) / 256, 256>>>();
    prep_kernel<<<(4096 * 1024 + 255) / 256, 256>>>(R, Kw, bias);

    dim3 grid(BATCH / BM, 4096 / BN);   // (32, 32)
    int pp = 0;

    for (int t = 0; t < SEQ_LEN; t++) {
        lstm_mma<<<grid, NTHREADS, SMEM_TOTAL>>>(inputs + t, SEQ_LEN, pp);
        pp ^= 1;
    }
    pred_kernel<<<BATCH / 8, 256>>>(w1, b1, w2, b2, out, 0, pp, 0);

    for (int j = 1; j < OUT_STEPS; j++) {
        lstm_mma<<<grid, NTHREADS, SMEM_TOTAL>>>(nullptr, 1, pp);
        pp ^= 1;
        pred_kernel<<<BATCH / 8, 256>>>(w1, b1, w2, b2, out, j, pp, 1);
    }
}